// round 16
// baseline (speedup 1.0000x reference)
#include <cuda_runtime.h>
#include <math.h>
#include <stdint.h>

// Static shapes for NativeSparseCrossAttention
#define B_      2
#define N_L     128
#define D_      512
#define N_T     16384
#define D_IN    256
#define NB      256
#define BS_     64
#define TOPK    16
#define RDIM    64
#define NHEAD   8
#define HD      64
#define NLAT    (B_ * N_L)     // 256

// Packed fp32x2 helpers (PTX-only)
__device__ __forceinline__ unsigned long long pk2(float v) {
    unsigned long long r;
    asm("mov.b64 %0, {%1, %1};" : "=l"(r) : "f"(v));
    return r;
}
__device__ __forceinline__ void fma2(unsigned long long& d,
                                     unsigned long long a,
                                     unsigned long long b) {
    asm("fma.rn.f32x2 %0, %1, %2, %0;" : "+l"(d) : "l"(a), "l"(b));
}
__device__ __forceinline__ void upk2(unsigned long long v, float& lo, float& hi) {
    asm("mov.b64 {%0, %1}, %2;" : "=f"(lo), "=f"(hi) : "l"(v));
}

// Slot usage (d_out, 512 floats per row r):
//   A: slot[g>>1][16+(g&1)*64 .. +64) = router-K of summary g     (K1)
//   B: slot[r][0:16) ints = idx ; slot[r][256:272) ints = idx copy (K2)
//   C: slot[r][0:256) = o heads 0-3 (K4 g=0); [256:512) = heads 4-7 (K4 g=1)
//   D: slot[r][0:512) = final row (K5, in-place)

// ---------------------------------------------------------------------------
__global__ __launch_bounds__(256) void nsca15_k1_summary(
    const float* __restrict__ bytes,
    const float* __restrict__ Wrk,
    const float* __restrict__ brk,
    float* __restrict__ dout)
{
    int g = blockIdx.x;
    const float* base = bytes + (size_t)g * BS_ * D_IN;
    __shared__ float s[D_IN];
    int d = threadIdx.x;
    float acc = 0.f;
    #pragma unroll 8
    for (int t = 0; t < BS_; ++t) acc += base[t * D_IN + d];
    s[d] = acc * (1.0f / 64.0f);
    __syncthreads();
    if (d < RDIM) {
        float r = brk[d];
        #pragma unroll 8
        for (int k = 0; k < D_IN; ++k) r += s[k] * Wrk[k * RDIM + d];
        dout[(size_t)(g >> 1) * 512 + 16 + (g & 1) * 64 + d] = r;
    }
}

// ---------------------------------------------------------------------------
// K2: router-Q + logits + top-16 -> idx at [0:16) AND copy at [256:272) ints.
__global__ __launch_bounds__(256) void nsca15_k2_topk(
    const float* __restrict__ latents,
    const float* __restrict__ Wrq,
    const float* __restrict__ brq,
    float* __restrict__ dout)
{
    int row = blockIdx.x;
    int b   = row >> 7;
    int tid = threadIdx.x;
    int w   = tid >> 5, lane = tid & 31;
    __shared__ float lat[D_];
    __shared__ float rq[RDIM];
    __shared__ float lg[NB];
    __shared__ float wv[8];
    __shared__ int   wi[8];

    lat[tid]       = latents[(size_t)row * D_ + tid];
    lat[tid + 256] = latents[(size_t)row * D_ + tid + 256];
    __syncthreads();

    {
        int col = tid >> 2, part = tid & 3;
        const float* Wc = Wrq + col;
        float a = 0.f;
        int k0 = part * 128;
        #pragma unroll 8
        for (int k = k0; k < k0 + 128; ++k) a += lat[k] * Wc[(size_t)k * RDIM];
        a += __shfl_xor_sync(0xffffffffu, a, 1);
        a += __shfl_xor_sync(0xffffffffu, a, 2);
        if (part == 0) rq[col] = a + brq[col];
    }
    __syncthreads();

    {
        int g = b * NB + tid;
        const float* rk = dout + (size_t)(g >> 1) * 512 + 16 + (g & 1) * 64;
        float a = 0.f;
        #pragma unroll 8
        for (int j = 0; j < RDIM; ++j) a += rq[j] * rk[j];
        lg[tid] = a;
    }
    __syncthreads();

    int* idx0 = (int*)dout + (size_t)row * 512;
    int* idx1 = idx0 + 256;
    for (int k = 0; k < TOPK; ++k) {
        float v = lg[tid]; int id = tid;
        #pragma unroll
        for (int off = 16; off; off >>= 1) {
            float ov = __shfl_xor_sync(0xffffffffu, v, off);
            int   oi = __shfl_xor_sync(0xffffffffu, id, off);
            if (ov > v || (ov == v && oi < id)) { v = ov; id = oi; }
        }
        if (lane == 0) { wv[w] = v; wi[w] = id; }
        __syncthreads();
        if (tid == 0) {
            float bv = wv[0]; int bi = wi[0];
            #pragma unroll
            for (int j = 1; j < 8; ++j)
                if (wv[j] > bv || (wv[j] == bv && wi[j] < bi)) { bv = wv[j]; bi = wi[j]; }
            idx0[k] = bi; idx1[k] = bi; lg[bi] = -INFINITY;
        }
        __syncthreads();
    }
}

// ---------------------------------------------------------------------------
// K4: head-split fused attention.  Block = (row, head-group of 4).  Grid 512.
// Shift-free softmax, cp.async double-staged x tiles, f32x2 math.
// smem (float offsets): XS@0[16640] UT@16640[1024] SP@17664[2048]
//                       PB@19712[256] SL2@19968[8] SF@19976[4] IDX@19980[16]
#define NS15_SMEM_FLOATS 20000
#define NS15_SMEM_BYTES  (NS15_SMEM_FLOATS * 4)

__global__ __launch_bounds__(256, 2) void nsca15_k4_attn(
    const float* __restrict__ bytes,
    const float* __restrict__ latents,
    const float* __restrict__ Wq,
    const float* __restrict__ Wk,
    const float* __restrict__ Wv,
    float* __restrict__ dout)
{
    extern __shared__ float sm[];
    float*  xsf = sm;
    float4* xs4 = (float4*)sm;
    float*  Ut  = sm + 16640;          // [256 ke][4 hl]
    float*  sP  = sm + 17664;          // [8 ks][4 hl][64 t]; alias sQ pre-loop
    float*  sQ  = sm + 17664;
    float*  pB  = sm + 19712;          // [64 t][4 hl]
    float*  sL2 = sm + 19968;          // [2 thalf][4 hl]
    float*  sF  = sm + 19976;          // [4 hl]
    int*    sIDX= (int*)(sm + 19980);

    int bx   = blockIdx.x;
    int row  = bx >> 1;
    int g    = bx & 1;                 // head group: heads 4g..4g+3
    int b    = row >> 7;
    int tid  = threadIdx.x;
    int w    = tid >> 5;
    int lane = tid & 31;

    float* slot = dout + (size_t)row * 512;

    // ---- prologue: idx (own copy), latents stage, init
    if (tid < TOPK) sIDX[tid] = ((const int*)slot)[g * 256 + tid];
    xsf[tid]       = latents[(size_t)row * D_ + tid];
    xsf[tid + 256] = latents[(size_t)row * D_ + tid + 256];
    if (tid < 8) sL2[tid] = 0.f;
    __syncthreads();

    // q for this head group: sQ[c] = lat . Wq[:, g*256+c],  c = tid
    {
        float a = 0.f;
        const float* Wc = Wq + g * 256 + tid;
        #pragma unroll 8
        for (int k = 0; k < D_; ++k) a += xsf[k] * Wc[(size_t)k * D_];
        __syncthreads();               // all lat reads done before tile0 copies
        sQ[tid] = a;
    }
    __syncthreads();

    // issue tile 0 staging (overwrites lat region of xs)
    const float4* xb = (const float4*)bytes + (size_t)(b * N_T) * 64;
    {
        const float4* src = xb + (size_t)sIDX[0] * 4096;
        #pragma unroll
        for (int j = 0; j < 16; ++j) {
            int e = tid + j * 256;
            uint32_t daddr = (uint32_t)__cvta_generic_to_shared(
                &xs4[(e >> 6) * 65 + (e & 63)]);
            asm volatile("cp.async.cg.shared.global [%0], [%1], 16;"
                :: "r"(daddr), "l"(src + e) : "memory");
        }
        asm volatile("cp.async.commit_group;" ::: "memory");
    }

    // ---- U[ke][hl] = sum_j Wk[ke][(4g+hl)*64+j] * q_hl[j]
    // 2 warps per local head: hl = w&3, half = w>>2 covers 128 ke each.
    {
        int hl = w & 3, half = w >> 2;
        float qx = sQ[hl * 64 + lane * 2];
        float qy = sQ[hl * 64 + lane * 2 + 1];
        int colb = g * 256 + hl * 64 + lane * 2;
        for (int d0 = half * 128; d0 < half * 128 + 128; d0 += 8) {
            float a0, a1, a2, a3, a4, a5, a6, a7;
            {
                const float* Wb = Wk + (size_t)d0 * D_ + colb;
                float2 t;
                t = *reinterpret_cast<const float2*>(Wb + 0 * D_); a0 = t.x * qx + t.y * qy;
                t = *reinterpret_cast<const float2*>(Wb + 1 * D_); a1 = t.x * qx + t.y * qy;
                t = *reinterpret_cast<const float2*>(Wb + 2 * D_); a2 = t.x * qx + t.y * qy;
                t = *reinterpret_cast<const float2*>(Wb + 3 * D_); a3 = t.x * qx + t.y * qy;
                t = *reinterpret_cast<const float2*>(Wb + 4 * D_); a4 = t.x * qx + t.y * qy;
                t = *reinterpret_cast<const float2*>(Wb + 5 * D_); a5 = t.x * qx + t.y * qy;
                t = *reinterpret_cast<const float2*>(Wb + 6 * D_); a6 = t.x * qx + t.y * qy;
                t = *reinterpret_cast<const float2*>(Wb + 7 * D_); a7 = t.x * qx + t.y * qy;
            }
            #pragma unroll
            for (int off = 16; off; off >>= 1) {
                a0 += __shfl_xor_sync(0xffffffffu, a0, off);
                a1 += __shfl_xor_sync(0xffffffffu, a1, off);
                a2 += __shfl_xor_sync(0xffffffffu, a2, off);
                a3 += __shfl_xor_sync(0xffffffffu, a3, off);
                a4 += __shfl_xor_sync(0xffffffffu, a4, off);
                a5 += __shfl_xor_sync(0xffffffffu, a5, off);
                a6 += __shfl_xor_sync(0xffffffffu, a6, off);
                a7 += __shfl_xor_sync(0xffffffffu, a7, off);
            }
            if (lane == 0) {
                Ut[(d0 + 0) * 4 + hl] = a0; Ut[(d0 + 1) * 4 + hl] = a1;
                Ut[(d0 + 2) * 4 + hl] = a2; Ut[(d0 + 3) * 4 + hl] = a3;
                Ut[(d0 + 4) * 4 + hl] = a4; Ut[(d0 + 5) * 4 + hl] = a5;
                Ut[(d0 + 6) * 4 + hl] = a6; Ut[(d0 + 7) * 4 + hl] = a7;
            }
        }
    }
    asm volatile("cp.async.wait_group 0;" ::: "memory");
    __syncthreads();                   // tile0 + Ut ready

    int dq = tid & 63, tp = tid >> 6;
    // ctx accumulators: cc[hp][comp], hp0=(h0,h1) hp1=(h2,h3) packed
    unsigned long long cc[2][4];
    #pragma unroll
    for (int i = 0; i < 2; ++i)
        #pragma unroll
        for (int j = 0; j < 4; ++j) cc[i][j] = 0ULL;

    // ---- mainloop: 16 iterations of 64 tokens
    for (int m = 0; m < TOPK; ++m) {
        // [A] score: warp = k-slice, lane = token (both halves)
        {
            unsigned long long sA[2] = {0ULL, 0ULL};
            unsigned long long sB[2] = {0ULL, 0ULL};
            #pragma unroll
            for (int i = 0; i < 8; ++i) {
                int k4 = w * 8 + i;
                float4 xa  = xs4[lane * 65 + k4];
                float4 xbv = xs4[(lane + 32) * 65 + k4];
                const ulonglong2* ub = (const ulonglong2*)(Ut + k4 * 16);
                #pragma unroll
                for (int c = 0; c < 4; ++c) {
                    ulonglong2 u = ub[c];              // 4 heads of k-elem
                    float xc = (c == 0) ? xa.x : (c == 1) ? xa.y : (c == 2) ? xa.z : xa.w;
                    float yc = (c == 0) ? xbv.x : (c == 1) ? xbv.y : (c == 2) ? xbv.z : xbv.w;
                    unsigned long long xc2 = pk2(xc), yc2 = pk2(yc);
                    fma2(sA[0], xc2, u.x); fma2(sA[1], xc2, u.y);
                    fma2(sB[0], yc2, u.x); fma2(sB[1], yc2, u.y);
                }
            }
            float* pa = sP + w * 256 + lane;           // [ks][hl][t]
            float* pb = pa + 32;
            float lo, hi;
            upk2(sA[0], lo, hi); pa[0] = lo;  pa[64] = hi;
            upk2(sA[1], lo, hi); pa[128] = lo; pa[192] = hi;
            upk2(sB[0], lo, hi); pb[0] = lo;  pb[64] = hi;
            upk2(sB[1], lo, hi); pb[128] = lo; pb[192] = hi;
        }
        __syncthreads();

        // issue staging for next tile (xs free)
        if (m < TOPK - 1) {
            const float4* src = xb + (size_t)sIDX[m + 1] * 4096;
            #pragma unroll
            for (int j = 0; j < 16; ++j) {
                int e = tid + j * 256;
                uint32_t daddr = (uint32_t)__cvta_generic_to_shared(
                    &xs4[(e >> 6) * 65 + (e & 63)]);
                asm volatile("cp.async.cg.shared.global [%0], [%1], 16;"
                    :: "r"(daddr), "l"(src + e) : "memory");
            }
            asm volatile("cp.async.commit_group;" ::: "memory");
        }

        // exp: warp w -> (hl = w&3, token half = w>>2); shift-free
        {
            int hl = w & 3;
            int t  = (w >> 2) * 32 + lane;
            const float* p = sP + hl * 64 + t;
            float v = p[0] + p[256] + p[512] + p[768]
                    + p[1024] + p[1280] + p[1536] + p[1792];
            float pe = __expf(v * 0.125f);
            pB[t * 4 + hl] = pe;
            float ts = pe;
            #pragma unroll
            for (int off = 16; off; off >>= 1)
                ts += __shfl_xor_sync(0xffffffffu, ts, off);
            if (lane == 0) sL2[(w >> 2) * 4 + hl] += ts;
        }
        __syncthreads();

        // ctx: x via coalesced LDG, probs via one LDS.128 per token
        {
            const float4* src = xb + (size_t)sIDX[m] * 4096;
            int t0 = tp * 16;
            #pragma unroll 4
            for (int t = t0; t < t0 + 16; ++t) {
                float4 xv = src[t * 64 + dq];
                ulonglong2 p = *(const ulonglong2*)(pB + t * 4);
                unsigned long long vx = pk2(xv.x), vy = pk2(xv.y);
                unsigned long long vz = pk2(xv.z), vw = pk2(xv.w);
                fma2(cc[0][0], p.x, vx); fma2(cc[0][1], p.x, vy);
                fma2(cc[0][2], p.x, vz); fma2(cc[0][3], p.x, vw);
                fma2(cc[1][0], p.y, vx); fma2(cc[1][1], p.y, vy);
                fma2(cc[1][2], p.y, vz); fma2(cc[1][3], p.y, vw);
            }
        }
        if (m < TOPK - 1)
            asm volatile("cp.async.wait_group 0;" ::: "memory");
        __syncthreads();               // copies visible; pB free for next iter
    }

    // ---- epilogue: reduce 4 token-partitions, normalize, o = ctx @ Wv_h
    {
        float4* red4 = xs4;            // [tp*4+hl][64 dq] float4
        #pragma unroll
        for (int hp = 0; hp < 2; ++hp) {
            float l0, h0, l1, h1, l2, h2, l3, h3;
            upk2(cc[hp][0], l0, h0);
            upk2(cc[hp][1], l1, h1);
            upk2(cc[hp][2], l2, h2);
            upk2(cc[hp][3], l3, h3);
            red4[(tp * 4 + 2 * hp) * 64 + dq]     = make_float4(l0, l1, l2, l3);
            red4[(tp * 4 + 2 * hp + 1) * 64 + dq] = make_float4(h0, h1, h2, h3);
        }
    }
    if (tid < 4) sF[tid] = 1.0f / (sL2[tid] + sL2[4 + tid]);
    __syncthreads();

    float* ctx_s = sP;                 // [4][260]
    for (int i = tid; i < 1024; i += 256) {
        int hl = i >> 8, k = i & 255;
        float v = xsf[(0 * 4 + hl) * 256 + k] + xsf[(1 * 4 + hl) * 256 + k]
                + xsf[(2 * 4 + hl) * 256 + k] + xsf[(3 * 4 + hl) * 256 + k];
        ctx_s[hl * 260 + k] = v * sF[hl];
    }
    __syncthreads();

    // o_hl[j] = sum_k ctx[hl][k] * Wv[k][(4g+hl)*64+j]; 2 warps/head (k-split)
    {
        int hl = w & 3, kh = w >> 2;
        float a0 = 0.f, a1 = 0.f;
        const float* ch = ctx_s + hl * 260;
        int colb = g * 256 + hl * 64 + lane * 2;
        #pragma unroll 4
        for (int k = kh * 128; k < kh * 128 + 128; ++k) {
            float2 wv = *reinterpret_cast<const float2*>(&Wv[(size_t)k * D_ + colb]);
            float cv = ch[k];
            a0 += cv * wv.x; a1 += cv * wv.y;
        }
        if (kh == 1) {
            pB[hl * 64 + lane * 2]     = a0;
            pB[hl * 64 + lane * 2 + 1] = a1;
        }
        __syncthreads();
        if (kh == 0) {
            slot[colb]     = a0 + pB[hl * 64 + lane * 2];
            slot[colb + 1] = a1 + pB[hl * 64 + lane * 2 + 1];
        }
    }
}

// ---------------------------------------------------------------------------
// K5 (cp.async, unchanged): out = o @ Wo, in-place.  64 blocks x 4 rows.
#define K5_SMEM_FLOATS 20480
#define K5_SMEM_BYTES  (K5_SMEM_FLOATS * 4)

__global__ __launch_bounds__(256) void nsca15_k5_oproj(
    const float* __restrict__ Wo,
    float* __restrict__ dout)
{
    extern __shared__ float s5[];
    float*  os   = s5;
    float4* red4 = (float4*)(s5 + 18432);

    int r0 = blockIdx.x * 4;
    int tid = threadIdx.x;
    int ks = tid >> 7;
    int ch = tid & 127;

    {
        const float4* src = (const float4*)(dout + (size_t)r0 * 512);
        float4* os4 = (float4*)os;
        os4[tid]       = src[tid];
        os4[tid + 256] = src[tid + 256];
    }

    const float4* Wo4 = (const float4*)Wo;
    uint32_t b0addr = (uint32_t)__cvta_generic_to_shared(s5 + 2048);
    uint32_t b1addr = b0addr + 8192 * 4;

    {
        #pragma unroll
        for (int j = 0; j < 8; ++j) {
            int e = tid + j * 256;
            asm volatile("cp.async.cg.shared.global [%0], [%1], 16;"
                :: "r"(b0addr + e * 16), "l"(Wo4 + e) : "memory");
        }
        asm volatile("cp.async.commit_group;" ::: "memory");
    }

    float4 a0 = {0,0,0,0}, a1 = {0,0,0,0}, a2 = {0,0,0,0}, a3 = {0,0,0,0};

    for (int c = 0; c < 32; ++c) {
        if (c + 1 < 32) {
            uint32_t dst = ((c + 1) & 1) ? b1addr : b0addr;
            const float4* gsrc = Wo4 + (size_t)(c + 1) * 2048;
            #pragma unroll
            for (int j = 0; j < 8; ++j) {
                int e = tid + j * 256;
                asm volatile("cp.async.cg.shared.global [%0], [%1], 16;"
                    :: "r"(dst + e * 16), "l"(gsrc + e) : "memory");
            }
            asm volatile("cp.async.commit_group;" ::: "memory");
            asm volatile("cp.async.wait_group 1;" ::: "memory");
        } else {
            asm volatile("cp.async.wait_group 0;" ::: "memory");
        }
        __syncthreads();

        const float4* Bc = (const float4*)(s5 + 2048 + (c & 1) * 8192);
        #pragma unroll
        for (int j = 0; j < 8; ++j) {
            int kl = ks + 2 * j;
            int k  = c * 16 + kl;
            float4 wv = Bc[kl * 128 + ch];
            float o0 = os[k], o1 = os[512 + k], o2 = os[1024 + k], o3 = os[1536 + k];
            a0.x += o0 * wv.x; a0.y += o0 * wv.y; a0.z += o0 * wv.z; a0.w += o0 * wv.w;
            a1.x += o1 * wv.x; a1.y += o1 * wv.y; a1.z += o1 * wv.z; a1.w += o1 * wv.w;
            a2.x += o2 * wv.x; a2.y += o2 * wv.y; a2.z += o2 * wv.z; a2.w += o2 * wv.w;
            a3.x += o3 * wv.x; a3.y += o3 * wv.y; a3.z += o3 * wv.z; a3.w += o3 * wv.w;
        }
        __syncthreads();
    }

    if (ks == 1) {
        red4[0 * 128 + ch] = a0;
        red4[1 * 128 + ch] = a1;
        red4[2 * 128 + ch] = a2;
        red4[3 * 128 + ch] = a3;
    }
    __syncthreads();
    if (ks == 0) {
        float4 b0 = red4[0 * 128 + ch];
        float4 b1 = red4[1 * 128 + ch];
        float4 b2 = red4[2 * 128 + ch];
        float4 b3 = red4[3 * 128 + ch];
        a0.x += b0.x; a0.y += b0.y; a0.z += b0.z; a0.w += b0.w;
        a1.x += b1.x; a1.y += b1.y; a1.z += b1.z; a1.w += b1.w;
        a2.x += b2.x; a2.y += b2.y; a2.z += b2.z; a2.w += b2.w;
        a3.x += b3.x; a3.y += b3.y; a3.z += b3.z; a3.w += b3.w;
        float4* out4 = (float4*)dout;
        out4[(size_t)(r0 + 0) * 128 + ch] = a0;
        out4[(size_t)(r0 + 1) * 128 + ch] = a1;
        out4[(size_t)(r0 + 2) * 128 + ch] = a2;
        out4[(size_t)(r0 + 3) * 128 + ch] = a3;
    }
}

// ---------------------------------------------------------------------------
extern "C" void kernel_launch(void* const* d_in, const int* in_sizes, int n_in,
                              void* d_out, int out_size)
{
    const float* latents = (const float*)d_in[0];
    const float* bytes   = (const float*)d_in[1];
    const float* rqw     = (const float*)d_in[2];
    const float* rqb     = (const float*)d_in[3];
    const float* rkw     = (const float*)d_in[4];
    const float* rkb     = (const float*)d_in[5];
    const float* Wq      = (const float*)d_in[6];
    const float* Wk      = (const float*)d_in[7];
    const float* Wv      = (const float*)d_in[8];
    const float* Wo      = (const float*)d_in[9];
    float* out = (float*)d_out;

    cudaFuncSetAttribute(nsca15_k4_attn,
                         cudaFuncAttributeMaxDynamicSharedMemorySize, NS15_SMEM_BYTES);
    cudaFuncSetAttribute(nsca15_k5_oproj,
                         cudaFuncAttributeMaxDynamicSharedMemorySize, K5_SMEM_BYTES);

    nsca15_k1_summary<<<B_ * NB, 256>>>(bytes, rkw, rkb, out);
    nsca15_k2_topk<<<NLAT, 256>>>(latents, rqw, rqb, out);
    nsca15_k4_attn<<<NLAT * 2, 256, NS15_SMEM_BYTES>>>(bytes, latents, Wq, Wk, Wv, out);
    nsca15_k5_oproj<<<64, 256, K5_SMEM_BYTES>>>(Wo, out);
}